// round 2
// baseline (speedup 1.0000x reference)
#include <cuda_runtime.h>
#include <cstdint>

#define N_NODES 50000
#define N_EDGES 800000
#define D_IN    256
#define H_DIM   96
#define BN_EPS  1e-5f

// ---------------- device scratch (no allocations allowed) ----------------
__device__ __align__(16) float g_h0[N_NODES * H_DIM];   // mlp0 output (gather source)
__device__ __align__(16) float g_z [N_NODES * H_DIM];   // h0 + segment_sum (scatter target)
__device__ __align__(16) float g_h [N_NODES * H_DIM];   // pre-BN linear1 output
__device__ float g_sum  [H_DIM];
__device__ float g_sumsq[H_DIM];
__device__ float g_scale[H_DIM];
__device__ float g_shift[H_DIM];
__device__ int   g_is64;                                // edge_index dtype flag

// ---------------- GEMM tiling ----------------
#define BM 64
#define BK 16

// =====================================================================
// Kernel 0: zero BN stat accumulators + detect edge_index dtype.
// int64 little-endian with values < 2^31 => every odd 32-bit word is 0.
// =====================================================================
__global__ void k_prolog(const int* __restrict__ ei32) {
    int t = threadIdx.x;
    if (t < H_DIM) { g_sum[t] = 0.f; g_sumsq[t] = 0.f; }
    if (t == 0) {
        int nz = 0;
#pragma unroll
        for (int i = 0; i < 64; i++) nz |= ei32[2 * i + 1];
        g_is64 = (nz == 0) ? 1 : 0;
    }
}

// =====================================================================
// Kernel 1: h0 = x @ W0^T + b0 ; z = h0     (K = 256)
// =====================================================================
__global__ __launch_bounds__(256) void k_gemm0(const float* __restrict__ x,
                                               const float* __restrict__ W0,
                                               const float* __restrict__ b0) {
    __shared__ float xs[BM][BK + 1];
    __shared__ float ws[H_DIM][BK + 1];

    const int tid = threadIdx.x;
    const int tx = tid & 15;
    const int ty = tid >> 4;
    const int row0 = blockIdx.x * BM;

    float acc[4][6];
#pragma unroll
    for (int i = 0; i < 4; i++)
#pragma unroll
        for (int j = 0; j < 6; j++) acc[i][j] = 0.f;

    for (int k0 = 0; k0 < D_IN; k0 += BK) {
#pragma unroll
        for (int t = 0; t < 4; t++) {
            int idx = tid + t * 256;
            int r = idx >> 4, k = idx & 15;
            int gr = row0 + r;
            xs[r][k] = (gr < N_NODES) ? x[gr * D_IN + k0 + k] : 0.f;
        }
#pragma unroll
        for (int t = 0; t < 6; t++) {
            int idx = tid + t * 256;
            int c = idx >> 4, k = idx & 15;
            ws[c][k] = W0[c * D_IN + k0 + k];
        }
        __syncthreads();
#pragma unroll
        for (int k = 0; k < BK; k++) {
            float a[4], b[6];
#pragma unroll
            for (int i = 0; i < 4; i++) a[i] = xs[ty * 4 + i][k];
#pragma unroll
            for (int j = 0; j < 6; j++) b[j] = ws[tx * 6 + j][k];
#pragma unroll
            for (int i = 0; i < 4; i++)
#pragma unroll
                for (int j = 0; j < 6; j++) acc[i][j] += a[i] * b[j];
        }
        __syncthreads();
    }

#pragma unroll
    for (int i = 0; i < 4; i++) {
        int gr = row0 + ty * 4 + i;
        if (gr < N_NODES) {
#pragma unroll
            for (int j = 0; j < 6; j++) {
                int c = tx * 6 + j;
                float v = acc[i][j] + b0[c];
                g_h0[gr * H_DIM + c] = v;
                g_z [gr * H_DIM + c] = v;
            }
        }
    }
}

// =====================================================================
// Kernel 2: scatter-add  z[dst] += h0[src]  via 16B vector reductions
// one thread per (edge, 4-col group): E * 24 work items
// =====================================================================
__global__ __launch_bounds__(256) void k_scatter(const void* __restrict__ ei) {
    unsigned idx = blockIdx.x * 256u + threadIdx.x;
    if (idx >= (unsigned)N_EDGES * 24u) return;
    unsigned e = idx / 24u;
    unsigned c = idx % 24u;
    int src, dst;
    if (g_is64) {
        const long long* p = (const long long*)ei;
        src = (int)p[e];
        dst = (int)p[N_EDGES + e];
    } else {
        const int* p = (const int*)ei;
        src = p[e];
        dst = p[N_EDGES + e];
    }
    if ((unsigned)src >= N_NODES || (unsigned)dst >= N_NODES) return;  // safety clamp
    const float4 v = *reinterpret_cast<const float4*>(&g_h0[src * H_DIM + c * 4]);
    float* p = &g_z[dst * H_DIM + c * 4];
    asm volatile("red.global.add.v4.f32 [%0], {%1,%2,%3,%4};"
                 :: "l"(p), "f"(v.x), "f"(v.y), "f"(v.z), "f"(v.w)
                 : "memory");
}

// =====================================================================
// Kernel 3: h = z @ W1^T + b1 ; accumulate column sum / sumsq   (K = 96)
// =====================================================================
__global__ __launch_bounds__(256) void k_gemm1(const float* __restrict__ W1,
                                               const float* __restrict__ b1) {
    __shared__ float xs[BM][BK + 1];
    __shared__ float ws[H_DIM][BK + 1];
    __shared__ float ssum[16][H_DIM];
    __shared__ float ssq [16][H_DIM];

    const int tid = threadIdx.x;
    const int tx = tid & 15;
    const int ty = tid >> 4;
    const int row0 = blockIdx.x * BM;

    float acc[4][6];
#pragma unroll
    for (int i = 0; i < 4; i++)
#pragma unroll
        for (int j = 0; j < 6; j++) acc[i][j] = 0.f;

    for (int k0 = 0; k0 < H_DIM; k0 += BK) {
#pragma unroll
        for (int t = 0; t < 4; t++) {
            int idx = tid + t * 256;
            int r = idx >> 4, k = idx & 15;
            int gr = row0 + r;
            xs[r][k] = (gr < N_NODES) ? g_z[gr * H_DIM + k0 + k] : 0.f;
        }
#pragma unroll
        for (int t = 0; t < 6; t++) {
            int idx = tid + t * 256;
            int c = idx >> 4, k = idx & 15;
            ws[c][k] = W1[c * H_DIM + k0 + k];
        }
        __syncthreads();
#pragma unroll
        for (int k = 0; k < BK; k++) {
            float a[4], b[6];
#pragma unroll
            for (int i = 0; i < 4; i++) a[i] = xs[ty * 4 + i][k];
#pragma unroll
            for (int j = 0; j < 6; j++) b[j] = ws[tx * 6 + j][k];
#pragma unroll
            for (int i = 0; i < 4; i++)
#pragma unroll
                for (int j = 0; j < 6; j++) acc[i][j] += a[i] * b[j];
        }
        __syncthreads();
    }

    float ps[6], pq[6];
#pragma unroll
    for (int j = 0; j < 6; j++) { ps[j] = 0.f; pq[j] = 0.f; }
#pragma unroll
    for (int i = 0; i < 4; i++) {
        int gr = row0 + ty * 4 + i;
        if (gr < N_NODES) {
#pragma unroll
            for (int j = 0; j < 6; j++) {
                int c = tx * 6 + j;
                float v = acc[i][j] + b1[c];
                g_h[gr * H_DIM + c] = v;
                ps[j] += v;
                pq[j] += v * v;
            }
        }
    }
#pragma unroll
    for (int j = 0; j < 6; j++) {
        ssum[ty][tx * 6 + j] = ps[j];
        ssq [ty][tx * 6 + j] = pq[j];
    }
    __syncthreads();
    if (tid < H_DIM) {
        float s = 0.f, q = 0.f;
#pragma unroll
        for (int r = 0; r < 16; r++) { s += ssum[r][tid]; q += ssq[r][tid]; }
        atomicAdd(&g_sum[tid],   s);
        atomicAdd(&g_sumsq[tid], q);
    }
}

// =====================================================================
// Kernel 4: finalize BN affine parameters (scale/shift per column)
// =====================================================================
__global__ void k_finalize(const float* __restrict__ gamma,
                           const float* __restrict__ beta) {
    int c = threadIdx.x;
    if (c < H_DIM) {
        float inv_n = 1.0f / (float)N_NODES;
        float mu  = g_sum[c] * inv_n;
        float var = g_sumsq[c] * inv_n - mu * mu;
        float sc  = gamma[c] * rsqrtf(var + BN_EPS);
        g_scale[c] = sc;
        g_shift[c] = beta[c] - mu * sc;
    }
}

// =====================================================================
// Kernel 5: out = relu(h*scale + shift) @ W2^T + b2    (K = 96)
// =====================================================================
__global__ __launch_bounds__(256) void k_gemm2(const float* __restrict__ W2,
                                               const float* __restrict__ b2,
                                               float* __restrict__ out) {
    __shared__ float xs[BM][BK + 1];
    __shared__ float ws[H_DIM][BK + 1];

    const int tid = threadIdx.x;
    const int tx = tid & 15;
    const int ty = tid >> 4;
    const int row0 = blockIdx.x * BM;

    float acc[4][6];
#pragma unroll
    for (int i = 0; i < 4; i++)
#pragma unroll
        for (int j = 0; j < 6; j++) acc[i][j] = 0.f;

    for (int k0 = 0; k0 < H_DIM; k0 += BK) {
#pragma unroll
        for (int t = 0; t < 4; t++) {
            int idx = tid + t * 256;
            int r = idx >> 4, k = idx & 15;
            int gr = row0 + r;
            int kk = k0 + k;
            float v = 0.f;
            if (gr < N_NODES) {
                v = g_h[gr * H_DIM + kk];
                v = fmaxf(v * g_scale[kk] + g_shift[kk], 0.f);
            }
            xs[r][k] = v;
        }
#pragma unroll
        for (int t = 0; t < 6; t++) {
            int idx = tid + t * 256;
            int c = idx >> 4, k = idx & 15;
            ws[c][k] = W2[c * H_DIM + k0 + k];
        }
        __syncthreads();
#pragma unroll
        for (int k = 0; k < BK; k++) {
            float a[4], b[6];
#pragma unroll
            for (int i = 0; i < 4; i++) a[i] = xs[ty * 4 + i][k];
#pragma unroll
            for (int j = 0; j < 6; j++) b[j] = ws[tx * 6 + j][k];
#pragma unroll
            for (int i = 0; i < 4; i++)
#pragma unroll
                for (int j = 0; j < 6; j++) acc[i][j] += a[i] * b[j];
        }
        __syncthreads();
    }

#pragma unroll
    for (int i = 0; i < 4; i++) {
        int gr = row0 + ty * 4 + i;
        if (gr < N_NODES) {
#pragma unroll
            for (int j = 0; j < 6; j++) {
                int c = tx * 6 + j;
                out[gr * H_DIM + c] = acc[i][j] + b2[c];
            }
        }
    }
}

// =====================================================================
// launch
// =====================================================================
extern "C" void kernel_launch(void* const* d_in, const int* in_sizes, int n_in,
                              void* d_out, int out_size) {
    const float* x     = (const float*)d_in[0];
    const void*  ei    = d_in[1];
    const float* W0    = (const float*)d_in[2];
    const float* b0    = (const float*)d_in[3];
    const float* W1    = (const float*)d_in[4];
    const float* b1    = (const float*)d_in[5];
    const float* gamma = (const float*)d_in[6];
    const float* beta  = (const float*)d_in[7];
    const float* W2    = (const float*)d_in[8];
    const float* b2    = (const float*)d_in[9];
    float*       out   = (float*)d_out;

    const int gemm_blocks = (N_NODES + BM - 1) / BM;          // 782
    const int scat_blocks = (N_EDGES * 24 + 255) / 256;       // 75000

    k_prolog<<<1, 128>>>((const int*)ei);
    k_gemm0<<<gemm_blocks, 256>>>(x, W0, b0);
    k_scatter<<<scat_blocks, 256>>>(ei);
    k_gemm1<<<gemm_blocks, 256>>>(W1, b1);
    k_finalize<<<1, H_DIM>>>(gamma, beta);
    k_gemm2<<<gemm_blocks, 256>>>(W2, b2, out);
}

// round 3
// speedup vs baseline: 1.1803x; 1.1803x over previous
#include <cuda_runtime.h>
#include <cstdint>

#define N_NODES 50000
#define N_EDGES 800000
#define D_IN    256
#define H_DIM   96
#define BN_EPS  1e-5f

#define BM 128
#define BK 16
#define N_BLK 391          // ceil(50000/128)
#define PSTRIDE 400        // padded partial stride (> N_BLK)

// ---------------- device scratch ----------------
__device__ __align__(16) float g_h0[N_NODES * H_DIM];
__device__ __align__(16) float g_z [N_NODES * H_DIM];
__device__ __align__(16) float g_h [N_NODES * H_DIM];
__device__ float g_psum [H_DIM * PSTRIDE];
__device__ float g_psq  [H_DIM * PSTRIDE];
__device__ float g_scale[H_DIM];
__device__ float g_shift[H_DIM];
__device__ int   g_is64;

// =====================================================================
// Fused tiled GEMM:  out[N,96] = A[N,KD] @ W[96,KD]^T + bias
// MODE 0: A=x (param), writes g_h0 and g_z, detects edge dtype
// MODE 1: A=g_z, writes g_h + per-block BN partial sums
// MODE 2: A=g_h with BN+ReLU applied on load, writes `out`
// 256 threads = 16x16; each thread: 8 rows x 6 cols.
// =====================================================================
template<int KD, int MODE>
__global__ __launch_bounds__(256) void k_gemm(const float* __restrict__ A,
                                              const float* __restrict__ W,
                                              const float* __restrict__ bias,
                                              float* __restrict__ out,
                                              const int* __restrict__ ei32) {
    __shared__ float xs[2][BK][BM + 4];
    __shared__ float ws[2][BK][H_DIM];
    __shared__ float ssum[16][H_DIM];
    __shared__ float ssq [16][H_DIM];
    __shared__ float s_scale[H_DIM];
    __shared__ float s_shift[H_DIM];

    const int tid  = threadIdx.x;
    const int tx   = tid & 15;
    const int ty   = tid >> 4;
    const int row0 = blockIdx.x * BM;

    if (MODE == 0) {
        if (blockIdx.x == 0 && tid == 0) {
            int nz = 0;
#pragma unroll
            for (int i = 0; i < 64; i++) nz |= ei32[2 * i + 1];
            g_is64 = (nz == 0) ? 1 : 0;
        }
    }
    if (MODE == 2) {
        if (tid < H_DIM) { s_scale[tid] = g_scale[tid]; s_shift[tid] = g_shift[tid]; }
        __syncthreads();
    }

    const float* Aptr = (MODE == 0) ? A : (MODE == 1 ? g_z : g_h);

    float acc[8][6];
#pragma unroll
    for (int i = 0; i < 8; i++)
#pragma unroll
        for (int j = 0; j < 6; j++) acc[i][j] = 0.f;

    float4 ra[2], rw[2];
    const int ar = tid >> 2;          // A row within tile (two passes: ar, ar+64)
    const int aq = tid & 3;           // k-quad
    const int wc = tid >> 2;          // W row (col of output)
    const int wq = tid & 3;

    auto ldgA = [&](int k0) {
#pragma unroll
        for (int t = 0; t < 2; t++) {
            int r  = ar + t * 64;
            int gr = row0 + r;
            float4 v = make_float4(0.f, 0.f, 0.f, 0.f);
            if (gr < N_NODES) {
                v = *reinterpret_cast<const float4*>(&Aptr[(size_t)gr * KD + k0 + aq * 4]);
                if (MODE == 2) {
                    int kg = k0 + aq * 4;
                    v.x = fmaxf(v.x * s_scale[kg    ] + s_shift[kg    ], 0.f);
                    v.y = fmaxf(v.y * s_scale[kg + 1] + s_shift[kg + 1], 0.f);
                    v.z = fmaxf(v.z * s_scale[kg + 2] + s_shift[kg + 2], 0.f);
                    v.w = fmaxf(v.w * s_scale[kg + 3] + s_shift[kg + 3], 0.f);
                }
            }
            ra[t] = v;
        }
    };
    auto ldgW = [&](int k0) {
        rw[0] = *reinterpret_cast<const float4*>(&W[(size_t)wc * KD + k0 + wq * 4]);
        if (tid < 128)
            rw[1] = *reinterpret_cast<const float4*>(&W[(size_t)(wc + 64) * KD + k0 + wq * 4]);
    };
    auto stsA = [&](int buf) {
#pragma unroll
        for (int t = 0; t < 2; t++) {
            int r = ar + t * 64;
            xs[buf][aq * 4 + 0][r] = ra[t].x;
            xs[buf][aq * 4 + 1][r] = ra[t].y;
            xs[buf][aq * 4 + 2][r] = ra[t].z;
            xs[buf][aq * 4 + 3][r] = ra[t].w;
        }
    };
    auto stsW = [&](int buf) {
        ws[buf][wq * 4 + 0][wc] = rw[0].x;
        ws[buf][wq * 4 + 1][wc] = rw[0].y;
        ws[buf][wq * 4 + 2][wc] = rw[0].z;
        ws[buf][wq * 4 + 3][wc] = rw[0].w;
        if (tid < 128) {
            ws[buf][wq * 4 + 0][wc + 64] = rw[1].x;
            ws[buf][wq * 4 + 1][wc + 64] = rw[1].y;
            ws[buf][wq * 4 + 2][wc + 64] = rw[1].z;
            ws[buf][wq * 4 + 3][wc + 64] = rw[1].w;
        }
    };

    constexpr int NT = KD / BK;
    ldgA(0); ldgW(0);
    stsA(0); stsW(0);
    __syncthreads();

    for (int t = 0; t < NT; t++) {
        if (t + 1 < NT) { ldgA((t + 1) * BK); ldgW((t + 1) * BK); }
        const int buf = t & 1;
#pragma unroll
        for (int k = 0; k < BK; k++) {
            const float4* xa = reinterpret_cast<const float4*>(&xs[buf][k][ty * 8]);
            float4 a0 = xa[0], a1 = xa[1];
            const float2* wb = reinterpret_cast<const float2*>(&ws[buf][k][tx * 6]);
            float2 b01 = wb[0], b23 = wb[1], b45 = wb[2];
            float a[8] = {a0.x, a0.y, a0.z, a0.w, a1.x, a1.y, a1.z, a1.w};
            float b[6] = {b01.x, b01.y, b23.x, b23.y, b45.x, b45.y};
#pragma unroll
            for (int i = 0; i < 8; i++)
#pragma unroll
                for (int j = 0; j < 6; j++) acc[i][j] += a[i] * b[j];
        }
        if (t + 1 < NT) { stsA((t + 1) & 1); stsW((t + 1) & 1); }
        __syncthreads();
    }

    // ---------------- epilogue ----------------
    float bb[6];
#pragma unroll
    for (int j = 0; j < 6; j++) bb[j] = bias[tx * 6 + j];

    if (MODE == 1) {
        float ps[6], pq[6];
#pragma unroll
        for (int j = 0; j < 6; j++) { ps[j] = 0.f; pq[j] = 0.f; }
#pragma unroll
        for (int i = 0; i < 8; i++) {
            int gr = row0 + ty * 8 + i;
            if (gr < N_NODES) {
#pragma unroll
                for (int j = 0; j < 6; j++) {
                    float v = acc[i][j] + bb[j];
                    g_h[(size_t)gr * H_DIM + tx * 6 + j] = v;
                    ps[j] += v;
                    pq[j] += v * v;
                }
            }
        }
#pragma unroll
        for (int j = 0; j < 6; j++) {
            ssum[ty][tx * 6 + j] = ps[j];
            ssq [ty][tx * 6 + j] = pq[j];
        }
        __syncthreads();
        if (tid < H_DIM) {
            float s = 0.f, q = 0.f;
#pragma unroll
            for (int r = 0; r < 16; r++) { s += ssum[r][tid]; q += ssq[r][tid]; }
            g_psum[tid * PSTRIDE + blockIdx.x] = s;
            g_psq [tid * PSTRIDE + blockIdx.x] = q;
        }
    } else {
#pragma unroll
        for (int i = 0; i < 8; i++) {
            int gr = row0 + ty * 8 + i;
            if (gr < N_NODES) {
#pragma unroll
                for (int j = 0; j < 6; j++) {
                    int c = tx * 6 + j;
                    float v = acc[i][j] + bb[j];
                    if (MODE == 0) {
                        g_h0[(size_t)gr * H_DIM + c] = v;
                        g_z [(size_t)gr * H_DIM + c] = v;
                    } else {
                        out[(size_t)gr * H_DIM + c] = v;
                    }
                }
            }
        }
    }
}

// =====================================================================
// Scatter-add  z[dst] += h0[src]  via 16B vector reductions
// =====================================================================
__global__ __launch_bounds__(256) void k_scatter(const void* __restrict__ ei) {
    unsigned idx = blockIdx.x * 256u + threadIdx.x;
    if (idx >= (unsigned)N_EDGES * 24u) return;
    unsigned e = idx / 24u;
    unsigned c = idx % 24u;
    int src, dst;
    if (g_is64) {
        const long long* p = (const long long*)ei;
        src = (int)p[e];
        dst = (int)p[N_EDGES + e];
    } else {
        const int* p = (const int*)ei;
        src = p[e];
        dst = p[N_EDGES + e];
    }
    if ((unsigned)src >= N_NODES || (unsigned)dst >= N_NODES) return;
    const float4 v = *reinterpret_cast<const float4*>(&g_h0[(size_t)src * H_DIM + c * 4]);
    float* p = &g_z[(size_t)dst * H_DIM + c * 4];
    asm volatile("red.global.add.v4.f32 [%0], {%1,%2,%3,%4};"
                 :: "l"(p), "f"(v.x), "f"(v.y), "f"(v.z), "f"(v.w)
                 : "memory");
}

// =====================================================================
// Finalize BN: one block per column, reduce 391 partials
// =====================================================================
__global__ void k_finalize(const float* __restrict__ gamma,
                           const float* __restrict__ beta) {
    const int c = blockIdx.x;
    const int t = threadIdx.x;
    __shared__ float sh[128], sh2[128];
    float s = 0.f, q = 0.f;
    for (int i = t; i < N_BLK; i += 128) {
        s += g_psum[c * PSTRIDE + i];
        q += g_psq [c * PSTRIDE + i];
    }
    sh[t] = s; sh2[t] = q;
    __syncthreads();
    for (int off = 64; off; off >>= 1) {
        if (t < off) { sh[t] += sh[t + off]; sh2[t] += sh2[t + off]; }
        __syncthreads();
    }
    if (t == 0) {
        float inv_n = 1.0f / (float)N_NODES;
        float mu  = sh[0] * inv_n;
        float var = sh2[0] * inv_n - mu * mu;
        float sc  = gamma[c] * rsqrtf(var + BN_EPS);
        g_scale[c] = sc;
        g_shift[c] = beta[c] - mu * sc;
    }
}

// =====================================================================
// launch
// =====================================================================
extern "C" void kernel_launch(void* const* d_in, const int* in_sizes, int n_in,
                              void* d_out, int out_size) {
    const float* x     = (const float*)d_in[0];
    const void*  ei    = d_in[1];
    const float* W0    = (const float*)d_in[2];
    const float* b0    = (const float*)d_in[3];
    const float* W1    = (const float*)d_in[4];
    const float* b1    = (const float*)d_in[5];
    const float* gamma = (const float*)d_in[6];
    const float* beta  = (const float*)d_in[7];
    const float* W2    = (const float*)d_in[8];
    const float* b2    = (const float*)d_in[9];
    float*       out   = (float*)d_out;

    const int scat_blocks = (N_EDGES * 24 + 255) / 256;

    k_gemm<D_IN, 0><<<N_BLK, 256>>>(x, W0, b0, nullptr, (const int*)ei);
    k_scatter<<<scat_blocks, 256>>>(ei);
    k_gemm<H_DIM, 1><<<N_BLK, 256>>>(nullptr, W1, b1, nullptr, nullptr);
    k_finalize<<<H_DIM, 128>>>(gamma, beta);
    k_gemm<H_DIM, 2><<<N_BLK, 256>>>(nullptr, W2, b2, out, nullptr);
}